// round 1
// baseline (speedup 1.0000x reference)
#include <cuda_runtime.h>
#include <cstdint>
#include <math.h>

// Problem constants (fixed by the reference)
#define T_STEPS 250
#define NCH     3
#define DFEAT   40
#define IN_DIM  120     // NCH*DFEAT
#define NHID    200
#define NBR     8
#define PER     15      // IN_DIM / NBR
#define PERP    16      // padded per-branch width (so f32x2 pairs never straddle)
#define XPAD    (NBR*PERP)   // 128
#define ODIM    35
#define NPARTS  7       // readout partial-sum parts (7*32 >= 200)
#define THREADS 256

// ---------------- packed f32x2 helpers (Blackwell) ----------------
__device__ __forceinline__ unsigned long long ffma2(unsigned long long a,
                                                    unsigned long long b,
                                                    unsigned long long c) {
    unsigned long long d;
    asm("fma.rn.f32x2 %0, %1, %2, %3;" : "=l"(d) : "l"(a), "l"(b), "l"(c));
    return d;
}
__device__ __forceinline__ unsigned long long pack2(float lo, float hi) {
    unsigned long long u;
    asm("mov.b64 %0, {%1, %2};" : "=l"(u) : "f"(lo), "f"(hi));
    return u;
}
__device__ __forceinline__ float2 unpack2(unsigned long long u) {
    float lo, hi;
    asm("mov.b64 {%0, %1}, %2;" : "=f"(lo), "=f"(hi) : "l"(u));
    return make_float2(lo, hi);
}

__device__ __forceinline__ float sigmoid_acc(float v) {
    // accurate sigmoid (used once per thread at init only)
    return 1.0f / (1.0f + expf(-v));
}

// One CTA per batch element. Thread n (< 200) owns neuron n.
// Masked dendritic weights live in 64 packed u64 registers per neuron thread.
// xt is staged in SMEM (branch-padded layout), with a register prefetch of
// step t+1 issued at the top of step t so DRAM latency hides under compute.
__global__ void __launch_bounds__(THREADS, 1) snn_kernel(
    const float* __restrict__ x,       // [B, 3, 250, 40]
    const float* __restrict__ W1,      // [200, 8, 120]
    const float* __restrict__ b1,      // [200]
    const float* __restrict__ tau_m1,  // [200]
    const float* __restrict__ tau_n1,  // [200, 8]
    const float* __restrict__ W2,      // [35, 200]
    const float* __restrict__ b2,      // [35]
    const float* __restrict__ tau_m2,  // [35]
    float* __restrict__ out)           // [B, 35]
{
    __shared__ __align__(16) float xbuf[XPAD];      // padded xt, pads stay 0
    __shared__ float spk_s[NHID];                   // spikes this step
    __shared__ float w2t[NHID][ODIM + 1];           // W2 transposed + padded
    __shared__ float psum[NPARTS][ODIM];            // readout partials
    __shared__ float accbuf[ODIM];                  // log-softmax staging

    const int tid = threadIdx.x;
    const int b   = blockIdx.x;

    // ---- init: W2 transposed into smem (conflict-free readout reads) ----
    for (int idx = tid; idx < NHID * ODIM; idx += THREADS) {
        int n = idx / ODIM, o = idx % ODIM;
        w2t[n][o] = W2[o * NHID + n];
    }
    // zero the pad slots (slot 16k+15 of each branch) — never overwritten
    if (tid < XPAD) xbuf[tid] = 0.0f;

    // ---- per-neuron params + packed weights into registers ----
    unsigned long long wp[64];      // 8 branches x 8 pairs (last pair hi = 0)
    float dstate[NBR];
    float beta[NBR];
    float alpha1 = 0.f, oma1 = 0.f, b1n = 0.f, mem1 = 0.f, spk = 0.f;
    if (tid < NHID) {
        const int n = tid;
        alpha1 = sigmoid_acc(tau_m1[n]);
        oma1   = 1.0f - alpha1;
        b1n    = b1[n];
#pragma unroll
        for (int k = 0; k < NBR; k++) {
            beta[k]   = sigmoid_acc(tau_n1[n * NBR + k]);
            dstate[k] = 0.0f;
            const float* wrow = W1 + (size_t)(n * NBR + k) * IN_DIM + k * PER;
#pragma unroll
            for (int p = 0; p < 8; p++) {
                float f0 = wrow[2 * p];
                float f1 = (2 * p + 1 < PER) ? wrow[2 * p + 1] : 0.0f;
                wp[k * 8 + p] = pack2(f0, f1);
            }
        }
    } else {
#pragma unroll
        for (int m = 0; m < 64; m++) wp[m] = 0ull;
#pragma unroll
        for (int k = 0; k < NBR; k++) { beta[k] = 0.f; dstate[k] = 0.f; }
    }

    // ---- readout role params ----
    const int o_ro    = tid % ODIM;          // for tid < NPARTS*ODIM = 245
    const int part_ro = tid / ODIM;
    const int rn0     = part_ro * 32;
    const int rn1     = (rn0 + 32 < NHID) ? rn0 + 32 : NHID;
    float alpha2 = 0.f, oma2 = 0.f, b2o = 0.f, mem2 = 0.f, acc = 0.f;
    if (tid < ODIM) {
        alpha2 = sigmoid_acc(tau_m2[tid]);
        oma2   = 1.0f - alpha2;
        b2o    = b2[tid];
    }

    // ---- x prefetch setup: threads 0..29 each own one float4 of xt ----
    const float* xbase = x + (size_t)b * NCH * T_STEPS * DFEAT;
    const int lc = tid / 10;                 // channel 0..2
    const int lv = tid % 10;                 // float4 index within 40
    float4 xr = make_float4(0.f, 0.f, 0.f, 0.f);
    if (tid < 30)
        xr = *(const float4*)(xbase + (size_t)lc * T_STEPS * DFEAT + lv * 4);

    __syncthreads();   // w2t, xbuf pads, xr(t=0) ready

    // ======================= time loop =======================
    for (int t = 0; t < T_STEPS; t++) {
        // scatter xt into branch-padded smem layout
        if (tid < 30) {
            const int ibase = lc * DFEAT + lv * 4;
            float v[4] = { xr.x, xr.y, xr.z, xr.w };
#pragma unroll
            for (int e = 0; e < 4; e++) {
                const int i = ibase + e;
                xbuf[(i / PER) * PERP + (i % PER)] = v[e];
            }
        }
        __syncthreads();   // S1: xbuf ready; prev-iter psum/spk consumers done

        // issue prefetch of t+1 (latency hides under this step's compute)
        if (tid < 30) {
            const int tn = (t + 1 < T_STEPS) ? t + 1 : t;
            xr = *(const float4*)(xbase + (size_t)lc * T_STEPS * DFEAT
                                  + (size_t)tn * DFEAT + lv * 4);
        }

        // ---- neuron phase: dendrites -> soma -> spike ----
        if (tid < NHID) {
            float l = b1n;
#pragma unroll
            for (int k = 0; k < NBR; k++) {
                const ulonglong2* xp = (const ulonglong2*)(xbuf + k * PERP);
                unsigned long long a0 = 0ull, a1 = 0ull;
#pragma unroll
                for (int q = 0; q < 4; q++) {
                    ulonglong2 xv = xp[q];
                    a0 = ffma2(wp[k * 8 + 2 * q],     xv.x, a0);
                    a1 = ffma2(wp[k * 8 + 2 * q + 1], xv.y, a1);
                }
                float2 s0 = unpack2(a0);
                float2 s1 = unpack2(a1);
                const float I = (s0.x + s1.x) + (s0.y + s1.y);
                const float dk = dstate[k];
                dstate[k] = fmaf(beta[k], dk - I, I);   // beta*d + (1-beta)*I
                l += dstate[k];
            }
            // soft-reset LIF: mem1 = a1*(mem1 - spk) + (1-a1)*l
            mem1 = fmaf(alpha1, mem1 - spk, oma1 * l);
            spk  = (mem1 > 1.0f) ? 1.0f : 0.0f;
            spk_s[tid] = spk;
        }
        __syncthreads();   // S2: spikes visible

        // ---- readout partials: 7 parts x 35 outputs ----
        if (tid < NPARTS * ODIM) {
            float s = 0.0f;
#pragma unroll 4
            for (int nn = rn0; nn < rn1; nn++)
                s = fmaf(spk_s[nn], w2t[nn][o_ro], s);
            psum[part_ro][o_ro] = s;
        }
        __syncthreads();   // S3: partials visible

        // ---- leaky readout integrator ----
        if (tid < ODIM) {
            float z = b2o;
#pragma unroll
            for (int p = 0; p < NPARTS; p++) z += psum[p][tid];
            mem2 = fmaf(alpha2, mem2, oma2 * z);
            acc += mem2;
        }
        // next iteration's S1 orders psum reads vs. next writes
    }

    // ======================= epilogue: log_softmax(acc/T) =======================
    if (tid < ODIM) accbuf[tid] = acc * (1.0f / (float)T_STEPS);
    __syncthreads();
    if (tid < ODIM) {
        float m = -INFINITY;
#pragma unroll
        for (int o = 0; o < ODIM; o++) m = fmaxf(m, accbuf[o]);
        float ssum = 0.0f;
#pragma unroll
        for (int o = 0; o < ODIM; o++) ssum += expf(accbuf[o] - m);
        out[(size_t)b * ODIM + tid] = accbuf[tid] - m - logf(ssum);
    }
}

extern "C" void kernel_launch(void* const* d_in, const int* in_sizes, int n_in,
                              void* d_out, int out_size) {
    const float* x      = (const float*)d_in[0];
    const float* W1     = (const float*)d_in[1];
    const float* b1     = (const float*)d_in[2];
    const float* tau_m1 = (const float*)d_in[3];
    const float* tau_n1 = (const float*)d_in[4];
    const float* W2     = (const float*)d_in[5];
    const float* b2     = (const float*)d_in[6];
    const float* tau_m2 = (const float*)d_in[7];
    float* out = (float*)d_out;

    const int B = in_sizes[0] / (NCH * T_STEPS * DFEAT);   // 512
    snn_kernel<<<B, THREADS>>>(x, W1, b1, tau_m1, tau_n1, W2, b2, tau_m2, out);
}

// round 4
// speedup vs baseline: 1.8147x; 1.8147x over previous
#include <cuda_runtime.h>
#include <cstdint>
#include <math.h>

// Problem constants (fixed by the reference)
#define T_STEPS 250
#define NCH     3
#define DFEAT   40
#define IN_DIM  120     // NCH*DFEAT
#define NHID    200
#define NBR     8
#define PER     15      // IN_DIM / NBR
#define PERP    16      // padded per-branch stride in xbuf (16B-aligned pairs)
#define XPAD    (NBR*PERP)   // 128
#define ODIM    35
#define NB      4       // batch elements per CTA
#define NPARTS  7       // readout partial-sum parts
#define THREADS 256

// ---------------- packed f32x2 helpers (sm_100a, PTX ISA 8.6) ----------------
__device__ __forceinline__ unsigned long long ffma2(unsigned long long a,
                                                    unsigned long long b,
                                                    unsigned long long c) {
    unsigned long long d;
    asm("fma.rn.f32x2 %0, %1, %2, %3;" : "=l"(d) : "l"(a), "l"(b), "l"(c));
    return d;
}
__device__ __forceinline__ unsigned long long add2(unsigned long long a,
                                                   unsigned long long b) {
    unsigned long long d;
    asm("add.rn.f32x2 %0, %1, %2;" : "=l"(d) : "l"(a), "l"(b));
    return d;
}
__device__ __forceinline__ unsigned long long pack2(float lo, float hi) {
    unsigned long long u;
    asm("mov.b64 %0, {%1, %2};" : "=l"(u) : "f"(lo), "f"(hi));
    return u;
}
__device__ __forceinline__ float2 unpack2(unsigned long long u) {
    float lo, hi;
    asm("mov.b64 {%0, %1}, %2;" : "=f"(lo), "=f"(hi) : "l"(u));
    return make_float2(lo, hi);
}
__device__ __forceinline__ float sigmoid_acc(float v) {
    return 1.0f / (1.0f + expf(-v));
}

// One CTA handles NB=4 batch elements. Thread n (<200) owns neuron n for all
// 4 batches (register-resident weights are batch-invariant). The 4 independent
// batch streams per thread supply the ILP the 1-batch version lacked, and
// grid = B/4 = 128 CTAs = exactly one wave on the chip.
__global__ void __launch_bounds__(THREADS, 1) snn_kernel(
    const float* __restrict__ x,       // [B, 3, 250, 40]
    const float* __restrict__ W1,      // [200, 8, 120]
    const float* __restrict__ b1,      // [200]
    const float* __restrict__ tau_m1,  // [200]
    const float* __restrict__ tau_n1,  // [200, 8]
    const float* __restrict__ W2,      // [35, 200]
    const float* __restrict__ b2,      // [35]
    const float* __restrict__ tau_m2,  // [35]
    float* __restrict__ out,           // [B, 35]
    int B)
{
    __shared__ __align__(16) float xbuf[NB][XPAD];        // branch-padded xt
    __shared__ __align__(16) float spk_s[NB][NHID];       // spikes this step
    __shared__ float psum[NPARTS][NB][ODIM + 1];          // readout partials
    __shared__ float accbuf[NB][ODIM];                    // log-softmax staging

    const int tid = threadIdx.x;
    const int b0  = blockIdx.x * NB;

    // ================= per-neuron params + packed weights =================
    unsigned long long wp[NBR * 7];   // 7 packed pairs per branch
    float w14[NBR];                   // 15th (scalar) weight per branch
    float beta[NBR];
    float dst[NB][NBR];
    float mem1[NB], spk[NB];
    float alpha1 = 0.f, oma1 = 0.f, b1n = 0.f;
#pragma unroll
    for (int bl = 0; bl < NB; bl++) {
        mem1[bl] = 0.f; spk[bl] = 0.f;
#pragma unroll
        for (int k = 0; k < NBR; k++) dst[bl][k] = 0.f;
    }
    if (tid < NHID) {
        const int n = tid;
        alpha1 = sigmoid_acc(tau_m1[n]);
        oma1   = 1.0f - alpha1;
        b1n    = b1[n];
#pragma unroll
        for (int k = 0; k < NBR; k++) {
            beta[k] = sigmoid_acc(tau_n1[n * NBR + k]);
            const float* wrow = W1 + (size_t)(n * NBR + k) * IN_DIM + k * PER;
#pragma unroll
            for (int j = 0; j < 7; j++)
                wp[k * 7 + j] = pack2(wrow[2 * j], wrow[2 * j + 1]);
            w14[k] = wrow[14];
        }
    } else {
#pragma unroll
        for (int m = 0; m < NBR * 7; m++) wp[m] = 0ull;
#pragma unroll
        for (int k = 0; k < NBR; k++) { beta[k] = 0.f; w14[k] = 0.f; }
    }

    // ================= readout params: W2 slice in registers =================
    const int p_ro = tid / ODIM;           // part 0..6 (tid < 245)
    const int o_ro = tid % ODIM;
    const int np0  = p_ro * 28;            // part 6 starts at 168, width 32
    const int wro  = (p_ro == 6) ? 32 : 28;
    float w2r[32];
#pragma unroll
    for (int j = 0; j < 32; j++) w2r[j] = 0.f;
    if (tid < NPARTS * ODIM) {
        for (int j = 0; j < 32; j++)
            if (j < wro) w2r[j] = W2[o_ro * NHID + np0 + j];
    }

    // ================= integrator params (threads 0..139) =================
    float alpha2 = 0.f, oma2 = 0.f, b2o = 0.f, mem2 = 0.f, acc = 0.f;
    if (tid < NB * ODIM) {
        alpha2 = sigmoid_acc(tau_m2[o_ro]);   // o_ro == tid % ODIM
        oma2   = 1.0f - alpha2;
        b2o    = b2[o_ro];
    }

    // ================= x prefetch: 240 threads x 2 floats =================
    // element g = 2*tid: bl = g/120, i = g%120 (i even, so the float2 stays
    // within one channel row of x)
    const float* pf_ptr = nullptr;
    float*       sl0 = nullptr;
    float*       sl1 = nullptr;
    float2 xr = make_float2(0.f, 0.f);
    if (tid < (NB * IN_DIM) / 2) {
        const int g   = 2 * tid;
        const int blp = g / IN_DIM;
        const int i0  = g % IN_DIM;
        const int c   = i0 / DFEAT;
        const int d   = i0 % DFEAT;
        int bb = b0 + blp; if (bb > B - 1) bb = B - 1;
        pf_ptr = x + ((size_t)bb * NCH + c) * T_STEPS * DFEAT + d;
        sl0 = &xbuf[blp][(i0 / PER) * PERP + (i0 % PER)];
        const int i1 = i0 + 1;
        sl1 = &xbuf[blp][(i1 / PER) * PERP + (i1 % PER)];
        xr = *(const float2*)pf_ptr;           // t = 0
    }

    __syncthreads();

    // ============================ time loop ============================
#pragma unroll 1
    for (int t = 0; t < T_STEPS; t++) {
        // scatter xt (register -> padded smem)
        if (pf_ptr) { *sl0 = xr.x; *sl1 = xr.y; }
        __syncthreads();   // S1: xbuf ready; prior psum/spk consumers done

        // prefetch t+1 (hides DRAM latency under this step's compute)
        if (pf_ptr) {
            const int tn = (t + 1 < T_STEPS) ? t + 1 : t;
            xr = *(const float2*)(pf_ptr + (size_t)tn * DFEAT);
        }

        // ---- neuron phase: dendrites -> soma -> spike, all 4 batches ----
        if (tid < NHID) {
#pragma unroll
            for (int bl = 0; bl < NB; bl++) {
                float l = b1n;
#pragma unroll
                for (int k = 0; k < NBR; k++) {
                    const ulonglong2* xp =
                        (const ulonglong2*)(&xbuf[bl][k * PERP]);
                    ulonglong2 q0 = xp[0];
                    ulonglong2 q1 = xp[1];
                    unsigned long long a0, a1;
                    a0 = ffma2(wp[k * 7 + 0], q0.x, 0ull);
                    a1 = ffma2(wp[k * 7 + 1], q0.y, 0ull);
                    a0 = ffma2(wp[k * 7 + 2], q1.x, a0);
                    a1 = ffma2(wp[k * 7 + 3], q1.y, a1);
                    ulonglong2 q2 = xp[2];
                    a0 = ffma2(wp[k * 7 + 4], q2.x, a0);
                    a1 = ffma2(wp[k * 7 + 5], q2.y, a1);
                    ulonglong2 q3 = xp[3];
                    a0 = ffma2(wp[k * 7 + 6], q3.x, a0);
                    float2 vv  = unpack2(add2(a0, a1));
                    float2 hx  = unpack2(q3.y);          // (x14, pad)
                    float  I   = fmaf(w14[k], hx.x, vv.x + vv.y);
                    float  dk  = dst[bl][k];
                    dk = fmaf(beta[k], dk - I, I);       // beta*d + (1-beta)*I
                    dst[bl][k] = dk;
                    l += dk;
                }
                // soft-reset LIF
                float m = fmaf(alpha1, mem1[bl] - spk[bl], oma1 * l);
                mem1[bl] = m;
                float s = (m > 1.0f) ? 1.0f : 0.0f;
                spk[bl] = s;
                spk_s[bl][tid] = s;
            }
        }
        __syncthreads();   // S2: spikes visible

        // ---- readout partials: W2 from registers, spikes via LDS.128 ----
        if (tid < NPARTS * ODIM) {
#pragma unroll
            for (int bl = 0; bl < NB; bl++) {
                const float4* sp = (const float4*)(&spk_s[bl][np0]);
                float s0 = 0.f, s1 = 0.f;
#pragma unroll
                for (int q = 0; q < 8; q++) {
                    float4 v = sp[q];
                    s0 = fmaf(v.x, w2r[4 * q + 0], s0);
                    s1 = fmaf(v.y, w2r[4 * q + 1], s1);
                    s0 = fmaf(v.z, w2r[4 * q + 2], s0);
                    s1 = fmaf(v.w, w2r[4 * q + 3], s1);
                }
                psum[p_ro][bl][o_ro] = s0 + s1;
            }
        }
        __syncthreads();   // S3: partials visible

        // ---- leaky readout integrator: thread (bl, o) ----
        if (tid < NB * ODIM) {
            const int bl = tid / ODIM;
            float z = b2o;
#pragma unroll
            for (int p = 0; p < NPARTS; p++) z += psum[p][bl][o_ro];
            mem2 = fmaf(alpha2, mem2, oma2 * z);
            acc += mem2;
        }
        // next iteration's S1 orders psum/spk reuse
    }

    // ==================== epilogue: log_softmax(acc/T) ====================
    if (tid < NB * ODIM) accbuf[tid / ODIM][o_ro] = acc * (1.0f / (float)T_STEPS);
    __syncthreads();
    if (tid < NB * ODIM) {
        const int bl = tid / ODIM;
        const int b  = b0 + bl;
        if (b < B) {
            float m = -INFINITY;
#pragma unroll
            for (int o = 0; o < ODIM; o++) m = fmaxf(m, accbuf[bl][o]);
            float ssum = 0.0f;
#pragma unroll
            for (int o = 0; o < ODIM; o++) ssum += expf(accbuf[bl][o] - m);
            out[(size_t)b * ODIM + o_ro] = accbuf[bl][o_ro] - m - logf(ssum);
        }
    }
}

extern "C" void kernel_launch(void* const* d_in, const int* in_sizes, int n_in,
                              void* d_out, int out_size) {
    const float* x      = (const float*)d_in[0];
    const float* W1     = (const float*)d_in[1];
    const float* b1     = (const float*)d_in[2];
    const float* tau_m1 = (const float*)d_in[3];
    const float* tau_n1 = (const float*)d_in[4];
    const float* W2     = (const float*)d_in[5];
    const float* b2     = (const float*)d_in[6];
    const float* tau_m2 = (const float*)d_in[7];
    float* out = (float*)d_out;

    const int B = in_sizes[0] / (NCH * T_STEPS * DFEAT);   // 512
    const int grid = (B + NB - 1) / NB;                    // 128
    snn_kernel<<<grid, THREADS>>>(x, W1, b1, tau_m1, tau_n1, W2, b2, tau_m2,
                                  out, B);
}